// round 1
// baseline (speedup 1.0000x reference)
#include <cuda_runtime.h>
#include <cuda_bf16.h>

// Problem constants
#define BB 16
#define SS 1024
#define PP 1024
#define DD 128
#define HH 8
#define HDIM 16
#define NGROUP 16384          // B*S == B*P
#define E_N 524288
#define EPS_F 1e-9f

// ---------------- device scratch (static, no allocs) ----------------
__device__ float g_qv1[NGROUP * 256];     // (row, [q(128) | v1(128)])
__device__ float g_kv2[NGROUP * 256];     // (col, [k(128) | v2(128)])
__device__ float g_el[E_N * 8];           // exp(score) per edge/head
__device__ int   g_rowflat[E_N];
__device__ int   g_colflat[E_N];
__device__ int   g_rowcnt[NGROUP];
__device__ int   g_colcnt[NGROUP];
__device__ int   g_rowptr[NGROUP];
__device__ int   g_colptr[NGROUP];
__device__ int   g_rowcur[NGROUP];
__device__ int   g_colcur[NGROUP];
__device__ int   g_rowedges[E_N];
__device__ int   g_coledges[E_N];
__device__ float g_rowheads[NGROUP * 128];
__device__ float g_colheads[NGROUP * 128];

// ---------------- zero counters ----------------
__global__ void zero_counts_kernel() {
    int i = blockIdx.x * blockDim.x + threadIdx.x;
    if (i < NGROUP) { g_rowcnt[i] = 0; g_colcnt[i] = 0; }
}

// ---------------- generic fp32 GEMM, K=128 fixed ----------------
// C[M,N] = A[M,128] @ B[128,N].  BM=BN=64, BK=32, 256 threads, 4x4 per thread.
__global__ void __launch_bounds__(256) gemm_k128(const float* __restrict__ A,
                                                 const float* __restrict__ Bm,
                                                 float* __restrict__ C,
                                                 int M, int N) {
    __shared__ float As[32][64];   // [k][m]
    __shared__ float Bs[32][64];   // [k][n]
    const int tx = threadIdx.x & 15;   // n direction
    const int ty = threadIdx.x >> 4;   // m direction
    const int m0 = blockIdx.y * 64;
    const int n0 = blockIdx.x * 64;

    float c[4][4] = {};

    for (int kk = 0; kk < 128; kk += 32) {
        // load A tile (64x32), transpose into As[k][m]
        {
            int f = threadIdx.x;
#pragma unroll
            for (int r = 0; r < 2; r++, f += 256) {
                int m  = f >> 3;
                int k4 = (f & 7) * 4;
                float4 v = *(const float4*)&A[(m0 + m) * 128 + kk + k4];
                As[k4 + 0][m] = v.x;
                As[k4 + 1][m] = v.y;
                As[k4 + 2][m] = v.z;
                As[k4 + 3][m] = v.w;
            }
        }
        // load B tile (32x64)
        {
            int f = threadIdx.x;
#pragma unroll
            for (int r = 0; r < 2; r++, f += 256) {
                int k  = f >> 4;
                int n4 = (f & 15) * 4;
                *(float4*)&Bs[k][n4] = *(const float4*)&Bm[(kk + k) * N + n0 + n4];
            }
        }
        __syncthreads();
#pragma unroll
        for (int k = 0; k < 32; k++) {
            float4 a4 = *(const float4*)&As[k][ty * 4];
            float4 b4 = *(const float4*)&Bs[k][tx * 4];
            float a[4] = {a4.x, a4.y, a4.z, a4.w};
            float b[4] = {b4.x, b4.y, b4.z, b4.w};
#pragma unroll
            for (int i = 0; i < 4; i++)
#pragma unroll
                for (int j = 0; j < 4; j++)
                    c[i][j] = fmaf(a[i], b[j], c[i][j]);
        }
        __syncthreads();
    }
#pragma unroll
    for (int i = 0; i < 4; i++) {
        float4 v = {c[i][0], c[i][1], c[i][2], c[i][3]};
        *(float4*)&C[(m0 + ty * 4 + i) * N + n0 + tx * 4] = v;
    }
}

// ---------------- edge logits: warp per edge (grid-stride) ----------------
// lane l: head h = l>>2, quarter q4 = l&3. Each lane handles HD/4=4 dims of the
// dot product and MS/4=8 hidden units of the per-head MLP.
__global__ void __launch_bounds__(256) edge_logits_kernel(
        const int* __restrict__ b_idx, const int* __restrict__ s_idx,
        const int* __restrict__ p_idx, const float* __restrict__ w,
        const float* __restrict__ msW1, const float* __restrict__ msb1,
        const float* __restrict__ msW2, const float* __restrict__ msb2) {
    const int lane = threadIdx.x & 31;
    const int h  = lane >> 2;
    const int q4 = lane & 3;
    const int mb = q4 * 8;

    // register-resident MLP weights for this lane's (head, hidden-chunk)
    float w1a[8], w1b[8], b1[8], w2[8];
#pragma unroll
    for (int j = 0; j < 8; j++) {
        w1a[j] = msW1[h * 64 + (mb + j)];        // msW1[h][0][m]
        w1b[j] = msW1[h * 64 + 32 + (mb + j)];   // msW1[h][1][m]
        b1[j]  = msb1[h * 32 + (mb + j)];
        w2[j]  = msW2[h * 32 + (mb + j)];
    }
    const float b2 = msb2[h];

    const int warp_global = (blockIdx.x * blockDim.x + threadIdx.x) >> 5;
    const int nwarps = (gridDim.x * blockDim.x) >> 5;

    for (int e = warp_global; e < E_N; e += nwarps) {
        const int b = b_idx[e];
        const int row = b * SS + s_idx[e];
        const int col = b * PP + p_idx[e];
        const float wv = w[e];

        float4 q = *(const float4*)&g_qv1[row * 256 + lane * 4];
        float4 k = *(const float4*)&g_kv2[col * 256 + lane * 4];
        float dot = q.x * k.x + q.y * k.y + q.z * k.z + q.w * k.w;
        dot += __shfl_xor_sync(0xffffffff, dot, 1);
        dot += __shfl_xor_sync(0xffffffff, dot, 2);
        const float logit = dot * 0.25f;   // 1/sqrt(HD=16)

        float part = 0.f;
#pragma unroll
        for (int j = 0; j < 8; j++) {
            float hid = fmaf(w1a[j], logit, fmaf(w1b[j], wv, b1[j]));
            hid = fmaxf(hid, 0.f);
            part = fmaf(hid, w2[j], part);
        }
        part += __shfl_xor_sync(0xffffffff, part, 1);
        part += __shfl_xor_sync(0xffffffff, part, 2);
        const float score = 10.0f * tanhf(part + b2);
        const float el = __expf(score);

        if (q4 == 0) g_el[e * 8 + h] = el;
        if (lane == 0) {
            g_rowflat[e] = row;
            g_colflat[e] = col;
            atomicAdd(&g_rowcnt[row], 1);
            atomicAdd(&g_colcnt[col], 1);
        }
    }
}

// ---------------- exclusive scan of 16384 counters (one block per side) ----
__global__ void __launch_bounds__(1024) scan_counts_kernel() {
    int* cnt = blockIdx.x ? g_colcnt : g_rowcnt;
    int* ptr = blockIdx.x ? g_colptr : g_rowptr;
    int* cur = blockIdx.x ? g_colcur : g_rowcur;
    __shared__ int sums[1024];
    const int t = threadIdx.x;
    const int base = t * 16;
    int local[16];
    int acc = 0;
#pragma unroll
    for (int i = 0; i < 16; i++) { local[i] = acc; acc += cnt[base + i]; }
    sums[t] = acc;
    __syncthreads();
    for (int off = 1; off < 1024; off <<= 1) {
        int v = 0;
        if (t >= off) v = sums[t - off];
        __syncthreads();
        if (t >= off) sums[t] += v;
        __syncthreads();
    }
    const int prefix = (t == 0) ? 0 : sums[t - 1];
#pragma unroll
    for (int i = 0; i < 16; i++) {
        int o = prefix + local[i];
        ptr[base + i] = o;
        cur[base + i] = o;
    }
}

// ---------------- scatter edge ids into CSR ----------------
__global__ void __launch_bounds__(256) scatter_edges_kernel() {
    const int e = blockIdx.x * blockDim.x + threadIdx.x;
    if (e >= E_N) return;
    const int r = g_rowflat[e];
    const int c = g_colflat[e];
    const int pr = atomicAdd(&g_rowcur[r], 1);
    g_rowedges[pr] = e;
    const int pc = atomicAdd(&g_colcur[c], 1);
    g_coledges[pc] = e;
}

// ---------------- gather-based softmax combine: warp per group ----------
// gw in [0, 32768): side 0 = rows (gather v2 from kv2), side 1 = cols (v1).
__global__ void __launch_bounds__(256) combine_kernel() {
    const int gw = (blockIdx.x * blockDim.x + threadIdx.x) >> 5;
    const int side = gw >> 14;
    const int g = gw & (NGROUP - 1);
    const int lane = threadIdx.x & 31;
    const int h = lane >> 2;

    const int* elist;
    const int* otherflat;
    const float* vsrc;
    float* dst;
    int start, n;
    if (side == 0) {
        start = g_rowptr[g]; n = g_rowcnt[g];
        elist = g_rowedges; otherflat = g_colflat;
        vsrc = g_kv2; dst = g_rowheads;
    } else {
        start = g_colptr[g]; n = g_colcnt[g];
        elist = g_coledges; otherflat = g_rowflat;
        vsrc = g_qv1; dst = g_colheads;
    }

    float dsum = 0.f;
    for (int i = 0; i < n; i++) {
        int e = elist[start + i];
        dsum += g_el[e * 8 + h];
    }
    const float inv = 1.0f / (dsum + EPS_F);

    float4 acc = {0.f, 0.f, 0.f, 0.f};
    for (int i = 0; i < n; i++) {
        int e = elist[start + i];
        float attn = g_el[e * 8 + h] * inv;
        int o = otherflat[e];
        float4 v = *(const float4*)&vsrc[o * 256 + 128 + lane * 4];
        acc.x = fmaf(attn, v.x, acc.x);
        acc.y = fmaf(attn, v.y, acc.y);
        acc.z = fmaf(attn, v.z, acc.z);
        acc.w = fmaf(attn, v.w, acc.w);
    }
    *(float4*)&dst[g * 128 + lane * 4] = acc;
}

// ---------------- launch ----------------
extern "C" void kernel_launch(void* const* d_in, const int* in_sizes, int n_in,
                              void* d_out, int out_size) {
    const float* x1   = (const float*)d_in[0];
    const float* x2   = (const float*)d_in[1];
    const int*   bi   = (const int*)d_in[2];
    const int*   si   = (const int*)d_in[3];
    const int*   pi   = (const int*)d_in[4];
    const float* w    = (const float*)d_in[5];
    const float* Wqv1 = (const float*)d_in[6];
    const float* Wkv2 = (const float*)d_in[7];
    const float* Wo1  = (const float*)d_in[8];
    const float* Wo2  = (const float*)d_in[9];
    const float* msW1 = (const float*)d_in[10];
    const float* msb1 = (const float*)d_in[11];
    const float* msW2 = (const float*)d_in[12];
    const float* msb2 = (const float*)d_in[13];
    float* out = (float*)d_out;

    float* g_qv1_p;      cudaGetSymbolAddress((void**)&g_qv1_p, g_qv1);
    float* g_kv2_p;      cudaGetSymbolAddress((void**)&g_kv2_p, g_kv2);
    float* g_rowheads_p; cudaGetSymbolAddress((void**)&g_rowheads_p, g_rowheads);
    float* g_colheads_p; cudaGetSymbolAddress((void**)&g_colheads_p, g_colheads);

    zero_counts_kernel<<<NGROUP / 256, 256>>>();
    gemm_k128<<<dim3(4, 256), 256>>>(x1, Wqv1, g_qv1_p, NGROUP, 256);
    gemm_k128<<<dim3(4, 256), 256>>>(x2, Wkv2, g_kv2_p, NGROUP, 256);
    edge_logits_kernel<<<2048, 256>>>(bi, si, pi, w, msW1, msb1, msW2, msb2);
    scan_counts_kernel<<<2, 1024>>>();
    scatter_edges_kernel<<<E_N / 256, 256>>>();
    combine_kernel<<<4096, 256>>>();
    gemm_k128<<<dim3(2, 256), 256>>>(g_rowheads_p, Wo1, out, NGROUP, 128);
    gemm_k128<<<dim3(2, 256), 256>>>(g_colheads_p, Wo2, out + NGROUP * 128, NGROUP, 128);
}

// round 3
// speedup vs baseline: 1.2981x; 1.2981x over previous
#include <cuda_runtime.h>
#include <cuda_bf16.h>

// Problem constants
#define BB 16
#define SS 1024
#define PP 1024
#define DD 128
#define HH 8
#define HDIM 16
#define NGROUP 16384          // B*S == B*P
#define E_N 524288
#define EPS_F 1e-9f

// ---------------- device scratch (static, no allocs) ----------------
__device__ float g_qv1[NGROUP * 256];     // (row, [q(128) | v1(128)])
__device__ float g_kv2[NGROUP * 256];     // (col, [k(128) | v2(128)])
__device__ float g_el[E_N * 8];           // exp(score) per edge/head
__device__ int   g_rowflat[E_N];
__device__ int   g_colflat[E_N];
__device__ int   g_rowcnt[NGROUP];
__device__ int   g_colcnt[NGROUP];
__device__ int   g_rowptr[NGROUP];
__device__ int   g_colptr[NGROUP];
__device__ int   g_rowcur[NGROUP];
__device__ int   g_colcur[NGROUP];
__device__ int   g_rowedges[E_N];
__device__ int   g_coledges[E_N];
__device__ float g_rowheads[NGROUP * 128];
__device__ float g_colheads[NGROUP * 128];

// ---------------- zero counters ----------------
__global__ void zero_counts_kernel() {
    int i = blockIdx.x * blockDim.x + threadIdx.x;
    if (i < NGROUP) { g_rowcnt[i] = 0; g_colcnt[i] = 0; }
}

// ---------------- fp32 GEMM, K=128 fixed, BM=128 BN=64 BK=16 ----------------
// 256 threads, 8x4 per-thread tile. 32 FFMA : 3 LDS.128 per k-step.
__global__ void __launch_bounds__(256) gemm_k128(const float* __restrict__ A,
                                                 const float* __restrict__ Bm,
                                                 float* __restrict__ C,
                                                 int N) {
    __shared__ float As[16][128];   // [k][m]
    __shared__ float Bs[16][64];    // [k][n]
    const int tid = threadIdx.x;
    const int tx = tid & 15;        // n direction (16 * 4 = 64)
    const int ty = tid >> 4;        // m direction (16 * 8 = 128)
    const int m0 = blockIdx.y * 128;
    const int n0 = blockIdx.x * 64;

    float c[8][4] = {};

    for (int kk = 0; kk < 128; kk += 16) {
        // A tile: 128 rows x 16 k, transpose into As[k][m]
#pragma unroll
        for (int r = 0; r < 2; r++) {
            int idx = tid + r * 256;
            int row = idx >> 2;
            int c4  = (idx & 3) * 4;
            float4 v = *(const float4*)&A[(m0 + row) * 128 + kk + c4];
            As[c4 + 0][row] = v.x;
            As[c4 + 1][row] = v.y;
            As[c4 + 2][row] = v.z;
            As[c4 + 3][row] = v.w;
        }
        // B tile: 16 k x 64 n
        {
            int row = tid >> 4;
            int c4  = (tid & 15) * 4;
            *(float4*)&Bs[row][c4] = *(const float4*)&Bm[(kk + row) * N + n0 + c4];
        }
        __syncthreads();
#pragma unroll
        for (int k = 0; k < 16; k++) {
            float4 a0 = *(const float4*)&As[k][ty * 8];
            float4 a1 = *(const float4*)&As[k][ty * 8 + 4];
            float4 b4 = *(const float4*)&Bs[k][tx * 4];
            float a[8] = {a0.x, a0.y, a0.z, a0.w, a1.x, a1.y, a1.z, a1.w};
            float b[4] = {b4.x, b4.y, b4.z, b4.w};
#pragma unroll
            for (int i = 0; i < 8; i++)
#pragma unroll
                for (int j = 0; j < 4; j++)
                    c[i][j] = fmaf(a[i], b[j], c[i][j]);
        }
        __syncthreads();
    }
#pragma unroll
    for (int i = 0; i < 8; i++) {
        float4 v = {c[i][0], c[i][1], c[i][2], c[i][3]};
        *(float4*)&C[(m0 + ty * 8 + i) * N + n0 + tx * 4] = v;
    }
}

// ---------------- fast tanh (saturating, __expf-based) ----------------
__device__ __forceinline__ float fast_tanh(float x) {
    // 1 - 2/(e^{2x}+1); e->inf => 1, e->0 => -1. __fdividef(2, inf) == 0.
    float e = __expf(2.0f * x);
    return 1.0f - __fdividef(2.0f, e + 1.0f);
}

// ---------------- edge logits: warp per 2 edges per iter ----------------
// lane l: head h = l>>2, quarter q4 = l&3.
__global__ void __launch_bounds__(256) edge_logits_kernel(
        const int* __restrict__ b_idx, const int* __restrict__ s_idx,
        const int* __restrict__ p_idx, const float* __restrict__ w,
        const float* __restrict__ msW1, const float* __restrict__ msb1,
        const float* __restrict__ msW2, const float* __restrict__ msb2) {
    const int lane = threadIdx.x & 31;
    const int h  = lane >> 2;
    const int q4 = lane & 3;
    const int mb = q4 * 8;

    // register-resident MLP weights for this lane's (head, hidden-chunk)
    float w1a[8], w1b[8], b1[8], w2[8];
#pragma unroll
    for (int j = 0; j < 8; j++) {
        w1a[j] = msW1[h * 64 + (mb + j)];        // msW1[h][0][m]
        w1b[j] = msW1[h * 64 + 32 + (mb + j)];   // msW1[h][1][m]
        b1[j]  = msb1[h * 32 + (mb + j)];
        w2[j]  = msW2[h * 32 + (mb + j)];
    }
    const float b2 = msb2[h];

    const int warp_global = (blockIdx.x * blockDim.x + threadIdx.x) >> 5;
    const int nwarps = (gridDim.x * blockDim.x) >> 5;

    for (int e0 = warp_global * 2; e0 < E_N; e0 += nwarps * 2) {
        const int e1 = e0 + 1;   // E_N even, stride even -> always valid
        const int bA = b_idx[e0], bB = b_idx[e1];
        const int rowA = bA * SS + s_idx[e0];
        const int rowB = bB * SS + s_idx[e1];
        const int colA = bA * PP + p_idx[e0];
        const int colB = bB * PP + p_idx[e1];
        const float wvA = w[e0], wvB = w[e1];

        float4 qA = *(const float4*)&g_qv1[rowA * 256 + lane * 4];
        float4 kA = *(const float4*)&g_kv2[colA * 256 + lane * 4];
        float4 qB = *(const float4*)&g_qv1[rowB * 256 + lane * 4];
        float4 kB = *(const float4*)&g_kv2[colB * 256 + lane * 4];

        float dA = qA.x * kA.x + qA.y * kA.y + qA.z * kA.z + qA.w * kA.w;
        float dB = qB.x * kB.x + qB.y * kB.y + qB.z * kB.z + qB.w * kB.w;
        dA += __shfl_xor_sync(0xffffffff, dA, 1);
        dB += __shfl_xor_sync(0xffffffff, dB, 1);
        dA += __shfl_xor_sync(0xffffffff, dA, 2);
        dB += __shfl_xor_sync(0xffffffff, dB, 2);
        const float logitA = dA * 0.25f;   // 1/sqrt(HD=16)
        const float logitB = dB * 0.25f;

        float pA = 0.f, pB = 0.f;
#pragma unroll
        for (int j = 0; j < 8; j++) {
            float hA = fmaf(w1a[j], logitA, fmaf(w1b[j], wvA, b1[j]));
            float hB = fmaf(w1a[j], logitB, fmaf(w1b[j], wvB, b1[j]));
            hA = fmaxf(hA, 0.f);
            hB = fmaxf(hB, 0.f);
            pA = fmaf(hA, w2[j], pA);
            pB = fmaf(hB, w2[j], pB);
        }
        pA += __shfl_xor_sync(0xffffffff, pA, 1);
        pB += __shfl_xor_sync(0xffffffff, pB, 1);
        pA += __shfl_xor_sync(0xffffffff, pA, 2);
        pB += __shfl_xor_sync(0xffffffff, pB, 2);

        const float elA = __expf(10.0f * fast_tanh(pA + b2));
        const float elB = __expf(10.0f * fast_tanh(pB + b2));

        if (q4 == 0) {
            g_el[e0 * 8 + h] = elA;
            g_el[e1 * 8 + h] = elB;
        }
        if (lane == 0) {
            g_rowflat[e0] = rowA;  g_rowflat[e1] = rowB;
            g_colflat[e0] = colA;  g_colflat[e1] = colB;
            atomicAdd(&g_rowcnt[rowA], 1);
            atomicAdd(&g_rowcnt[rowB], 1);
            atomicAdd(&g_colcnt[colA], 1);
            atomicAdd(&g_colcnt[colB], 1);
        }
    }
}

// ---------------- exclusive scan of 16384 counters (one block per side) ----
__global__ void __launch_bounds__(1024) scan_counts_kernel() {
    int* cnt = blockIdx.x ? g_colcnt : g_rowcnt;
    int* ptr = blockIdx.x ? g_colptr : g_rowptr;
    int* cur = blockIdx.x ? g_colcur : g_rowcur;
    __shared__ int sums[1024];
    const int t = threadIdx.x;
    const int base = t * 16;
    int local[16];
    int acc = 0;
#pragma unroll
    for (int i = 0; i < 16; i++) { local[i] = acc; acc += cnt[base + i]; }
    sums[t] = acc;
    __syncthreads();
    for (int off = 1; off < 1024; off <<= 1) {
        int v = 0;
        if (t >= off) v = sums[t - off];
        __syncthreads();
        if (t >= off) sums[t] += v;
        __syncthreads();
    }
    const int prefix = (t == 0) ? 0 : sums[t - 1];
#pragma unroll
    for (int i = 0; i < 16; i++) {
        int o = prefix + local[i];
        ptr[base + i] = o;
        cur[base + i] = o;
    }
}

// ---------------- scatter edge ids into CSR ----------------
__global__ void __launch_bounds__(256) scatter_edges_kernel() {
    const int e = blockIdx.x * blockDim.x + threadIdx.x;
    if (e >= E_N) return;
    const int r = g_rowflat[e];
    const int c = g_colflat[e];
    const int pr = atomicAdd(&g_rowcur[r], 1);
    g_rowedges[pr] = e;
    const int pc = atomicAdd(&g_colcur[c], 1);
    g_coledges[pc] = e;
}

// ---------------- gather-based softmax combine: warp per group ----------
// Single pass: acc = sum(el*v); out = acc / (sum(el) + eps).
__global__ void __launch_bounds__(256) combine_kernel() {
    const int gw = (blockIdx.x * blockDim.x + threadIdx.x) >> 5;
    const int side = gw >> 14;
    const int g = gw & (NGROUP - 1);
    const int lane = threadIdx.x & 31;
    const int h = lane >> 2;

    const int* elist;
    const int* otherflat;
    const float* vsrc;
    float* dst;
    int start, n;
    if (side == 0) {
        start = g_rowptr[g]; n = g_rowcnt[g];
        elist = g_rowedges; otherflat = g_colflat;
        vsrc = g_kv2; dst = g_rowheads;
    } else {
        start = g_colptr[g]; n = g_colcnt[g];
        elist = g_coledges; otherflat = g_rowflat;
        vsrc = g_qv1; dst = g_colheads;
    }

    float dsum = 0.f;
    float4 acc = {0.f, 0.f, 0.f, 0.f};
    int i = 0;
    for (; i + 1 < n; i += 2) {
        int eA = elist[start + i];
        int eB = elist[start + i + 1];
        float elA = g_el[eA * 8 + h];
        float elB = g_el[eB * 8 + h];
        int oA = otherflat[eA];
        int oB = otherflat[eB];
        float4 vA = *(const float4*)&vsrc[oA * 256 + 128 + lane * 4];
        float4 vB = *(const float4*)&vsrc[oB * 256 + 128 + lane * 4];
        dsum += elA + elB;
        acc.x = fmaf(elA, vA.x, fmaf(elB, vB.x, acc.x));
        acc.y = fmaf(elA, vA.y, fmaf(elB, vB.y, acc.y));
        acc.z = fmaf(elA, vA.z, fmaf(elB, vB.z, acc.z));
        acc.w = fmaf(elA, vA.w, fmaf(elB, vB.w, acc.w));
    }
    if (i < n) {
        int e = elist[start + i];
        float el = g_el[e * 8 + h];
        int o = otherflat[e];
        float4 v = *(const float4*)&vsrc[o * 256 + 128 + lane * 4];
        dsum += el;
        acc.x = fmaf(el, v.x, acc.x);
        acc.y = fmaf(el, v.y, acc.y);
        acc.z = fmaf(el, v.z, acc.z);
        acc.w = fmaf(el, v.w, acc.w);
    }
    const float inv = 1.0f / (dsum + EPS_F);
    acc.x *= inv; acc.y *= inv; acc.z *= inv; acc.w *= inv;
    *(float4*)&dst[g * 128 + lane * 4] = acc;
}

// ---------------- launch ----------------
extern "C" void kernel_launch(void* const* d_in, const int* in_sizes, int n_in,
                              void* d_out, int out_size) {
    const float* x1   = (const float*)d_in[0];
    const float* x2   = (const float*)d_in[1];
    const int*   bi   = (const int*)d_in[2];
    const int*   si   = (const int*)d_in[3];
    const int*   pi   = (const int*)d_in[4];
    const float* w    = (const float*)d_in[5];
    const float* Wqv1 = (const float*)d_in[6];
    const float* Wkv2 = (const float*)d_in[7];
    const float* Wo1  = (const float*)d_in[8];
    const float* Wo2  = (const float*)d_in[9];
    const float* msW1 = (const float*)d_in[10];
    const float* msb1 = (const float*)d_in[11];
    const float* msW2 = (const float*)d_in[12];
    const float* msb2 = (const float*)d_in[13];
    float* out = (float*)d_out;

    float* g_qv1_p;      cudaGetSymbolAddress((void**)&g_qv1_p, g_qv1);
    float* g_kv2_p;      cudaGetSymbolAddress((void**)&g_kv2_p, g_kv2);
    float* g_rowheads_p; cudaGetSymbolAddress((void**)&g_rowheads_p, g_rowheads);
    float* g_colheads_p; cudaGetSymbolAddress((void**)&g_colheads_p, g_colheads);

    zero_counts_kernel<<<NGROUP / 256, 256>>>();
    gemm_k128<<<dim3(4, 128), 256>>>(x1, Wqv1, g_qv1_p, 256);
    gemm_k128<<<dim3(4, 128), 256>>>(x2, Wkv2, g_kv2_p, 256);
    edge_logits_kernel<<<1184, 256>>>(bi, si, pi, w, msW1, msb1, msW2, msb2);
    scan_counts_kernel<<<2, 1024>>>();
    scatter_edges_kernel<<<E_N / 256, 256>>>();
    combine_kernel<<<4096, 256>>>();
    gemm_k128<<<dim3(2, 128), 256>>>(g_rowheads_p, Wo1, out, 128);
    gemm_k128<<<dim3(2, 128), 256>>>(g_colheads_p, Wo2, out + NGROUP * 128, 128);
}

// round 5
// speedup vs baseline: 1.2996x; 1.0012x over previous
#include <cuda_runtime.h>
#include <cuda_bf16.h>

// Problem constants
#define BB 16
#define SS 1024
#define PP 1024
#define DD 128
#define HH 8
#define HDIM 16
#define NGROUP 16384          // B*S == B*P
#define E_N 524288
#define EPS_F 1e-9f

typedef unsigned long long ull;

// ---------------- device scratch (static, no allocs) ----------------
__device__ float g_qv1[NGROUP * 256];     // (row, [q(128) | v1(128)])
__device__ float g_kv2[NGROUP * 256];     // (col, [k(128) | v2(128)])
__device__ float g_logit[E_N * 8];        // raw dot/sqrt(HD) per edge/head
__device__ float g_el[E_N * 8];           // exp(score) per edge/head
__device__ int   g_rowflat[E_N];
__device__ int   g_colflat[E_N];
__device__ int   g_rowcnt[NGROUP];
__device__ int   g_colcnt[NGROUP];
__device__ int   g_rowptr[NGROUP];
__device__ int   g_colptr[NGROUP];
__device__ int   g_rowcur[NGROUP];
__device__ int   g_colcur[NGROUP];
__device__ int   g_rowedges[E_N];
__device__ int   g_coledges[E_N];
__device__ float g_rowheads[NGROUP * 128];
__device__ float g_colheads[NGROUP * 128];

// ---------------- f32x2 helpers ----------------
__device__ __forceinline__ ull pack2_dup(float x) {
    ull r;
    asm("mov.b64 %0, {%1, %1};" : "=l"(r) : "r"(__float_as_uint(x)));
    return r;
}
__device__ __forceinline__ void ffma2(ull& d, ull a, ull b) {
    asm("fma.rn.f32x2 %0, %1, %2, %0;" : "+l"(d) : "l"(a), "l"(b));
}
__device__ __forceinline__ float f2_lo(ull v) { return __uint_as_float((unsigned)v); }
__device__ __forceinline__ float f2_hi(ull v) { return __uint_as_float((unsigned)(v >> 32)); }

// ---------------- zero counters ----------------
__global__ void zero_counts_kernel() {
    int i = blockIdx.x * blockDim.x + threadIdx.x;
    if (i < NGROUP) { g_rowcnt[i] = 0; g_colcnt[i] = 0; }
}

// ---------------- fp32 GEMM via f32x2, K=128, BM=128 BN=64 BK=16 ----------
// 256 threads, 8x4 per-thread tile packed as 4x4 f32x2 pairs along m.
__global__ void __launch_bounds__(256) gemm_k128(const float* __restrict__ A,
                                                 const float* __restrict__ Bm,
                                                 float* __restrict__ C,
                                                 int N) {
    __shared__ float As[16][128];   // [k][m]
    __shared__ float Bs[16][64];    // [k][n]
    const int tid = threadIdx.x;
    const int tx = tid & 15;        // n direction (16 * 4 = 64)
    const int ty = tid >> 4;        // m direction (16 * 8 = 128)
    const int m0 = blockIdx.y * 128;
    const int n0 = blockIdx.x * 64;

    ull c2[4][4];
#pragma unroll
    for (int i = 0; i < 4; i++)
#pragma unroll
        for (int j = 0; j < 4; j++) c2[i][j] = 0ull;

    for (int kk = 0; kk < 128; kk += 16) {
        // A tile: 128 rows x 16 k, transpose into As[k][m]
#pragma unroll
        for (int r = 0; r < 2; r++) {
            int idx = tid + r * 256;
            int row = idx >> 2;
            int c4  = (idx & 3) * 4;
            float4 v = *(const float4*)&A[(m0 + row) * 128 + kk + c4];
            As[c4 + 0][row] = v.x;
            As[c4 + 1][row] = v.y;
            As[c4 + 2][row] = v.z;
            As[c4 + 3][row] = v.w;
        }
        // B tile: 16 k x 64 n
        {
            int row = tid >> 4;
            int c4  = (tid & 15) * 4;
            *(float4*)&Bs[row][c4] = *(const float4*)&Bm[(kk + row) * N + n0 + c4];
        }
        __syncthreads();
#pragma unroll
        for (int k = 0; k < 16; k++) {
            const ull* ap = (const ull*)&As[k][ty * 8];   // 4 m-pairs
            ull a0 = ap[0], a1 = ap[1], a2 = ap[2], a3 = ap[3];
            float4 b4 = *(const float4*)&Bs[k][tx * 4];
            ull bb0 = pack2_dup(b4.x);
            ull bb1 = pack2_dup(b4.y);
            ull bb2 = pack2_dup(b4.z);
            ull bb3 = pack2_dup(b4.w);
            ffma2(c2[0][0], a0, bb0); ffma2(c2[0][1], a0, bb1);
            ffma2(c2[0][2], a0, bb2); ffma2(c2[0][3], a0, bb3);
            ffma2(c2[1][0], a1, bb0); ffma2(c2[1][1], a1, bb1);
            ffma2(c2[1][2], a1, bb2); ffma2(c2[1][3], a1, bb3);
            ffma2(c2[2][0], a2, bb0); ffma2(c2[2][1], a2, bb1);
            ffma2(c2[2][2], a2, bb2); ffma2(c2[2][3], a2, bb3);
            ffma2(c2[3][0], a3, bb0); ffma2(c2[3][1], a3, bb1);
            ffma2(c2[3][2], a3, bb2); ffma2(c2[3][3], a3, bb3);
        }
        __syncthreads();
    }
#pragma unroll
    for (int i2 = 0; i2 < 4; i2++) {
        float4 vlo = {f2_lo(c2[i2][0]), f2_lo(c2[i2][1]), f2_lo(c2[i2][2]), f2_lo(c2[i2][3])};
        float4 vhi = {f2_hi(c2[i2][0]), f2_hi(c2[i2][1]), f2_hi(c2[i2][2]), f2_hi(c2[i2][3])};
        *(float4*)&C[(m0 + ty * 8 + 2 * i2 + 0) * N + n0 + tx * 4] = vlo;
        *(float4*)&C[(m0 + ty * 8 + 2 * i2 + 1) * N + n0 + tx * 4] = vhi;
    }
}

// ---------------- fast tanh (saturating, __expf-based) ----------------
__device__ __forceinline__ float fast_tanh(float x) {
    float e = __expf(2.0f * x);
    return 1.0f - __fdividef(2.0f, e + 1.0f);
}

// ---------------- phase 1: edge gather + dot products ----------------
// warp per 2 edges; lane l: head h=l>>2, quarter q4=l&3.
__global__ void __launch_bounds__(256) edge_dot_kernel(
        const int* __restrict__ b_idx, const int* __restrict__ s_idx,
        const int* __restrict__ p_idx) {
    const int lane = threadIdx.x & 31;
    const int h  = lane >> 2;
    const int q4 = lane & 3;

    const int warp_global = (blockIdx.x * blockDim.x + threadIdx.x) >> 5;
    const int nwarps = (gridDim.x * blockDim.x) >> 5;

    for (int e0 = warp_global * 2; e0 < E_N; e0 += nwarps * 2) {
        const int e1 = e0 + 1;
        const int bA = b_idx[e0], bB = b_idx[e1];
        const int rowA = bA * SS + s_idx[e0];
        const int rowB = bB * SS + s_idx[e1];
        const int colA = bA * PP + p_idx[e0];
        const int colB = bB * PP + p_idx[e1];

        float4 qA = *(const float4*)&g_qv1[rowA * 256 + lane * 4];
        float4 kA = *(const float4*)&g_kv2[colA * 256 + lane * 4];
        float4 qB = *(const float4*)&g_qv1[rowB * 256 + lane * 4];
        float4 kB = *(const float4*)&g_kv2[colB * 256 + lane * 4];

        float dA = qA.x * kA.x + qA.y * kA.y + qA.z * kA.z + qA.w * kA.w;
        float dB = qB.x * kB.x + qB.y * kB.y + qB.z * kB.z + qB.w * kB.w;
        dA += __shfl_xor_sync(0xffffffff, dA, 1);
        dB += __shfl_xor_sync(0xffffffff, dB, 1);
        dA += __shfl_xor_sync(0xffffffff, dA, 2);
        dB += __shfl_xor_sync(0xffffffff, dB, 2);

        if (q4 == 0) {
            g_logit[e0 * 8 + h] = dA * 0.25f;   // 1/sqrt(HD=16)
            g_logit[e1 * 8 + h] = dB * 0.25f;
        }
        if (lane == 0) {
            g_rowflat[e0] = rowA;  g_rowflat[e1] = rowB;
            g_colflat[e0] = colA;  g_colflat[e1] = colB;
            atomicAdd(&g_rowcnt[rowA], 1);
            atomicAdd(&g_rowcnt[rowB], 1);
            atomicAdd(&g_colcnt[colA], 1);
            atomicAdd(&g_colcnt[colB], 1);
        }
    }
}

// ---------------- phase 2: per-(edge,head) MLP + tanh + exp ------------
// thread t handles (e = t>>3, h = t&7). Weights in smem, conflict-free.
__global__ void __launch_bounds__(256) edge_mlp_kernel(
        const float* __restrict__ w,
        const float* __restrict__ msW1, const float* __restrict__ msb1,
        const float* __restrict__ msW2, const float* __restrict__ msb2) {
    __shared__ float4 sw[8 * 33];      // head h, unit j at [h*33 + j]
    __shared__ float sb2[8];
    const int tid = threadIdx.x;
    {
        int hh = tid >> 5, j = tid & 31;
        sw[hh * 33 + j] = make_float4(msW1[hh * 64 + j],
                                      msW1[hh * 64 + 32 + j],
                                      msb1[hh * 32 + j],
                                      msW2[hh * 32 + j]);
        if (tid < 8) sb2[tid] = msb2[tid];
    }
    __syncthreads();

    const int t = blockIdx.x * 256 + tid;   // t = e*8 + h
    const int h = t & 7;
    const int e = t >> 3;
    const float logit = g_logit[t];
    const float wv = w[e];
    const float4* wp = &sw[h * 33];

    float out = 0.f;
#pragma unroll 8
    for (int j = 0; j < 32; j++) {
        float4 c = wp[j];
        float hid = fmaf(c.x, logit, fmaf(c.y, wv, c.z));
        hid = fmaxf(hid, 0.f);
        out = fmaf(hid, c.w, out);
    }
    g_el[t] = __expf(10.0f * fast_tanh(out + sb2[h]));
}

// ---------------- exclusive scan of 16384 counters (one block per side) ----
__global__ void __launch_bounds__(1024) scan_counts_kernel() {
    int* cnt = blockIdx.x ? g_colcnt : g_rowcnt;
    int* ptr = blockIdx.x ? g_colptr : g_rowptr;
    int* cur = blockIdx.x ? g_colcur : g_rowcur;
    __shared__ int sums[1024];
    const int t = threadIdx.x;
    const int base = t * 16;
    int local[16];
    int acc = 0;
#pragma unroll
    for (int i = 0; i < 16; i++) { local[i] = acc; acc += cnt[base + i]; }
    sums[t] = acc;
    __syncthreads();
    for (int off = 1; off < 1024; off <<= 1) {
        int v = 0;
        if (t >= off) v = sums[t - off];
        __syncthreads();
        if (t >= off) sums[t] += v;
        __syncthreads();
    }
    const int prefix = (t == 0) ? 0 : sums[t - 1];
#pragma unroll
    for (int i = 0; i < 16; i++) {
        int o = prefix + local[i];
        ptr[base + i] = o;
        cur[base + i] = o;
    }
}

// ---------------- scatter edge ids into CSR ----------------
__global__ void __launch_bounds__(256) scatter_edges_kernel() {
    const int e = blockIdx.x * blockDim.x + threadIdx.x;
    if (e >= E_N) return;
    const int r = g_rowflat[e];
    const int c = g_colflat[e];
    const int pr = atomicAdd(&g_rowcur[r], 1);
    g_rowedges[pr] = e;
    const int pc = atomicAdd(&g_colcur[c], 1);
    g_coledges[pc] = e;
}

// ---------------- gather-based softmax combine: warp per group ----------
__global__ void __launch_bounds__(256) combine_kernel() {
    const int gw = (blockIdx.x * blockDim.x + threadIdx.x) >> 5;
    const int side = gw >> 14;
    const int g = gw & (NGROUP - 1);
    const int lane = threadIdx.x & 31;
    const int h = lane >> 2;

    const int* elist;
    const int* otherflat;
    const float* vsrc;
    float* dst;
    int start, n;
    if (side == 0) {
        start = g_rowptr[g]; n = g_rowcnt[g];
        elist = g_rowedges; otherflat = g_colflat;
        vsrc = g_kv2; dst = g_rowheads;
    } else {
        start = g_colptr[g]; n = g_colcnt[g];
        elist = g_coledges; otherflat = g_rowflat;
        vsrc = g_qv1; dst = g_colheads;
    }

    float dsum = 0.f;
    float4 acc = {0.f, 0.f, 0.f, 0.f};
    int i = 0;
    for (; i + 1 < n; i += 2) {
        int eA = elist[start + i];
        int eB = elist[start + i + 1];
        float elA = g_el[eA * 8 + h];
        float elB = g_el[eB * 8 + h];
        int oA = otherflat[eA];
        int oB = otherflat[eB];
        float4 vA = *(const float4*)&vsrc[oA * 256 + 128 + lane * 4];
        float4 vB = *(const float4*)&vsrc[oB * 256 + 128 + lane * 4];
        dsum += elA + elB;
        acc.x = fmaf(elA, vA.x, fmaf(elB, vB.x, acc.x));
        acc.y = fmaf(elA, vA.y, fmaf(elB, vB.y, acc.y));
        acc.z = fmaf(elA, vA.z, fmaf(elB, vB.z, acc.z));
        acc.w = fmaf(elA, vA.w, fmaf(elB, vB.w, acc.w));
    }
    if (i < n) {
        int e = elist[start + i];
        float el = g_el[e * 8 + h];
        int o = otherflat[e];
        float4 v = *(const float4*)&vsrc[o * 256 + 128 + lane * 4];
        dsum += el;
        acc.x = fmaf(el, v.x, acc.x);
        acc.y = fmaf(el, v.y, acc.y);
        acc.z = fmaf(el, v.z, acc.z);
        acc.w = fmaf(el, v.w, acc.w);
    }
    const float inv = 1.0f / (dsum + EPS_F);
    acc.x *= inv; acc.y *= inv; acc.z *= inv; acc.w *= inv;
    *(float4*)&dst[g * 128 + lane * 4] = acc;
}

// ---------------- launch ----------------
extern "C" void kernel_launch(void* const* d_in, const int* in_sizes, int n_in,
                              void* d_out, int out_size) {
    const float* x1   = (const float*)d_in[0];
    const float* x2   = (const float*)d_in[1];
    const int*   bi   = (const int*)d_in[2];
    const int*   si   = (const int*)d_in[3];
    const int*   pi   = (const int*)d_in[4];
    const float* w    = (const float*)d_in[5];
    const float* Wqv1 = (const float*)d_in[6];
    const float* Wkv2 = (const float*)d_in[7];
    const float* Wo1  = (const float*)d_in[8];
    const float* Wo2  = (const float*)d_in[9];
    const float* msW1 = (const float*)d_in[10];
    const float* msb1 = (const float*)d_in[11];
    const float* msW2 = (const float*)d_in[12];
    const float* msb2 = (const float*)d_in[13];
    float* out = (float*)d_out;

    float* g_qv1_p;      cudaGetSymbolAddress((void**)&g_qv1_p, g_qv1);
    float* g_kv2_p;      cudaGetSymbolAddress((void**)&g_kv2_p, g_kv2);
    float* g_rowheads_p; cudaGetSymbolAddress((void**)&g_rowheads_p, g_rowheads);
    float* g_colheads_p; cudaGetSymbolAddress((void**)&g_colheads_p, g_colheads);

    zero_counts_kernel<<<NGROUP / 256, 256>>>();
    gemm_k128<<<dim3(4, 128), 256>>>(x1, Wqv1, g_qv1_p, 256);
    gemm_k128<<<dim3(4, 128), 256>>>(x2, Wkv2, g_kv2_p, 256);
    edge_dot_kernel<<<888, 256>>>(bi, si, pi);
    edge_mlp_kernel<<<E_N * 8 / 256, 256>>>(w, msW1, msb1, msW2, msb2);
    scan_counts_kernel<<<2, 1024>>>();
    scatter_edges_kernel<<<E_N / 256, 256>>>();
    combine_kernel<<<4096, 256>>>();
    gemm_k128<<<dim3(2, 128), 256>>>(g_rowheads_p, Wo1, out, 128);
    gemm_k128<<<dim3(2, 128), 256>>>(g_colheads_p, Wo2, out + NGROUP * 128, 128);
}